// round 14
// baseline (speedup 1.0000x reference)
#include <cuda_runtime.h>
#include <cuda_fp16.h>

#define BN 8192
#define DN 128
#define KN 256
#define INV_T (1.0f / 0.07f)

// Scratch (no allocations allowed anywhere)
__device__ unsigned g_z1q[BN * DN / 4];  // z1n quantized int8, per-row scale (1 MB)
__device__ unsigned g_z2q[BN * DN / 4];  // z2n quantized int8 * 127       (1 MB)
__device__ float    g_f1[BN];            // per-row logit factor: maxa*INV_T/(127*127)
__device__ float    g_pos[BN];           // positive logit (fp32-exact path)
__device__ float    g_partial[BN];       // per-row loss
__device__ int      g_is64;              // index dtype flag
__device__ int      g_count;             // last-block counter (reset each replay)

// ---------------------------------------------------------------------------
// Normalize z1/z2 in fp32; quantize both to int8 (z1 per-row scale, z2 flat
// 127); positive logit in full fp32. One warp per row. Block 0 / warp 0 also
// detects index dtype (values < 8192 => int64 has all-zero high words) and
// resets the completion counter for this graph replay.
// ---------------------------------------------------------------------------
__global__ void norm_kernel(const float* __restrict__ z1,
                            const float* __restrict__ z2,
                            const int* __restrict__ raw) {
    const int warp = threadIdx.x >> 5;
    const int lane = threadIdx.x & 31;

    if (blockIdx.x == 0 && warp == 0) {
        const int nz = (raw[2 * lane + 1] != 0) | (raw[2 * (lane + 32) + 1] != 0);
        const unsigned bal = __ballot_sync(0xffffffffu, nz);
        if (lane == 0) { g_is64 = (bal == 0u) ? 1 : 0; g_count = 0; }
    }

    const int row = blockIdx.x * 8 + warp;
    if (row >= BN) return;

    float4 a = reinterpret_cast<const float4*>(z1 + (size_t)row * DN)[lane];
    float4 b = reinterpret_cast<const float4*>(z2 + (size_t)row * DN)[lane];

    float sa = a.x * a.x + a.y * a.y + a.z * a.z + a.w * a.w;
    float sb = b.x * b.x + b.y * b.y + b.z * b.z + b.w * b.w;
    #pragma unroll
    for (int o = 16; o; o >>= 1) {
        sa += __shfl_xor_sync(0xffffffffu, sa, o);
        sb += __shfl_xor_sync(0xffffffffu, sb, o);
    }
    const float inva = 1.0f / fmaxf(sqrtf(sa), 1e-12f);
    const float invb = 1.0f / fmaxf(sqrtf(sb), 1e-12f);

    a.x *= inva; a.y *= inva; a.z *= inva; a.w *= inva;
    b.x *= invb; b.y *= invb; b.z *= invb; b.w *= invb;

    // per-row max |z1 elem| for tight quantization scale
    float m = fmaxf(fmaxf(fabsf(a.x), fabsf(a.y)), fmaxf(fabsf(a.z), fabsf(a.w)));
    #pragma unroll
    for (int o = 16; o; o >>= 1) m = fmaxf(m, __shfl_xor_sync(0xffffffffu, m, o));
    m = fmaxf(m, 1e-12f);
    const float s1 = 127.0f / m;

    const int qa0 = __float2int_rn(a.x * s1);
    const int qa1 = __float2int_rn(a.y * s1);
    const int qa2 = __float2int_rn(a.z * s1);
    const int qa3 = __float2int_rn(a.w * s1);
    g_z1q[(size_t)row * 32 + lane] =
        (qa0 & 0xff) | ((qa1 & 0xff) << 8) | ((qa2 & 0xff) << 16) | (qa3 << 24);

    const int qb0 = __float2int_rn(b.x * 127.0f);
    const int qb1 = __float2int_rn(b.y * 127.0f);
    const int qb2 = __float2int_rn(b.z * 127.0f);
    const int qb3 = __float2int_rn(b.w * 127.0f);
    g_z2q[(size_t)row * 32 + lane] =
        (qb0 & 0xff) | ((qb1 & 0xff) << 8) | ((qb2 & 0xff) << 16) | (qb3 << 24);

    if (lane == 0) g_f1[row] = m * (INV_T / (127.0f * 127.0f));

    // positive logit, full fp32
    float d = a.x * b.x + a.y * b.y + a.z * b.z + a.w * b.w;
    #pragma unroll
    for (int o = 16; o; o >>= 1) d += __shfl_xor_sync(0xffffffffu, d, o);
    if (lane == 0) g_pos[row] = d * INV_T;
}

// ---------------------------------------------------------------------------
// Gather v5: int8 rows (128B = one L2 line), DP4A dot engine, MLP=8.
// __launch_bounds__(256,4) gives 64 regs/thread so all 8 LDG.128 of a warp's
// batch are issued back-to-back (phase 2) before any consumption (phase 3),
// hiding L2 latency behind memory-level parallelism instead of occupancy.
// One z2 row per 8-LANE group; warp covers its 32 negatives in 8 waves of 4.
// Lane (q,s) owns negative w*32 + 4*s + q -> exactly one __expf per thread.
// The last block to finish performs the deterministic mean.
// ---------------------------------------------------------------------------
__global__ void __launch_bounds__(256, 4)
gather_kernel(const int* __restrict__ raw, float* __restrict__ out) {
    __shared__ float s_red[8];
    __shared__ float s_sum[256];
    __shared__ bool  s_last;

    const int b    = blockIdx.x;
    const int t    = threadIdx.x;
    const int w    = t >> 5;
    const int lane = t & 31;
    const int s    = lane & 7;    // lane within 8-lane row group
    const int q    = lane >> 3;   // which of 4 rows per LDG wave

    // hoist the per-row scalars so their L2 latency overlaps the dot loop
    const float f1  = __ldg(&g_f1[b]);
    const float pos = __ldg(&g_pos[b]);

    // this lane's 16 z1 bytes (elements [s*16, s*16+16))
    const uint4 z1v =
        reinterpret_cast<const uint4*>(g_z1q)[(size_t)b * 8 + s];

    const int kbase = b * KN + w * 32 + lane;
    const int myidx = g_is64 ? raw[2 * kbase] : raw[kbase];

    // Phase 1: all row indices via shuffle (no memory dependence).
    int rows[8];
    #pragma unroll
    for (int i = 0; i < 8; i++)
        rows[i] = __shfl_sync(0xffffffffu, myidx, 4 * i + q);

    // Phase 2: batch all 8 LDG.128 (32 data regs) -> MLP = 8 per warp.
    const uint4* z2p = reinterpret_cast<const uint4*>(g_z2q);
    uint4 v[8];
    #pragma unroll
    for (int i = 0; i < 8; i++)
        v[i] = z2p[(size_t)rows[i] * 8 + s];

    // Phase 3: consume in order; 8-lane group reduce; lane s==i owns wave i.
    int mydot = 0;
    #pragma unroll
    for (int i = 0; i < 8; i++) {
        int acc;
        acc = __dp4a((int)v[i].x, (int)z1v.x, 0);
        acc = __dp4a((int)v[i].y, (int)z1v.y, acc);
        acc = __dp4a((int)v[i].z, (int)z1v.z, acc);
        acc = __dp4a((int)v[i].w, (int)z1v.w, acc);
        acc += __shfl_xor_sync(0xffffffffu, acc, 4);
        acc += __shfl_xor_sync(0xffffffffu, acc, 2);
        acc += __shfl_xor_sync(0xffffffffu, acc, 1);
        if (s == i) mydot = acc;  // lane owns negative w*32 + 4*s + q
    }

    // |logit| <= ~14.3 -> no max-shift needed in fp32.
    float e = __expf((float)mydot * f1);
    #pragma unroll
    for (int o = 16; o; o >>= 1) e += __shfl_xor_sync(0xffffffffu, e, o);
    if (lane == 0) s_red[w] = e;
    __syncthreads();

    if (t == 0) {
        float tot = s_red[0] + s_red[1] + s_red[2] + s_red[3]
                  + s_red[4] + s_red[5] + s_red[6] + s_red[7];
        tot += __expf(pos);
        g_partial[b] = logf(tot) - pos;   // -log_softmax(logits)[0]
        __threadfence();
        const int c = atomicAdd(&g_count, 1);
        s_last = (c == BN - 1);
    }
    __syncthreads();

    // Last finishing block performs the mean (deterministic order).
    if (s_last) {
        const float4* p4 = reinterpret_cast<const float4*>(g_partial);
        float a = 0.0f;
        #pragma unroll
        for (int j = 0; j < 8; j++) {
            const float4 vv = __ldcg(p4 + t + j * 256);
            a += (vv.x + vv.y) + (vv.z + vv.w);
        }
        s_sum[t] = a;
        __syncthreads();
        #pragma unroll
        for (int o = 128; o; o >>= 1) {
            if (t < o) s_sum[t] += s_sum[t + o];
            __syncthreads();
        }
        if (t == 0) out[0] = s_sum[0] / (float)BN;
    }
}

extern "C" void kernel_launch(void* const* d_in, const int* in_sizes, int n_in,
                              void* d_out, int out_size) {
    const float* z1  = (const float*)d_in[0];
    const float* z2  = (const float*)d_in[1];
    const int*   neg = (const int*)d_in[2];   // raw view; width detected on-device
    float* out = (float*)d_out;

    norm_kernel<<<BN / 8, 256>>>(z1, z2, neg);
    gather_kernel<<<BN, 256>>>(neg, out);
}

// round 16
// speedup vs baseline: 1.2976x; 1.2976x over previous
#include <cuda_runtime.h>
#include <cuda_fp16.h>

#define BN 8192
#define DN 128
#define KN 256
#define INV_T (1.0f / 0.07f)

// Scratch (no allocations allowed anywhere)
__device__ unsigned g_z1q[BN * DN / 4];  // z1n quantized int8, per-row scale (1 MB)
__device__ unsigned g_z2q[BN * DN / 4];  // z2n quantized int8 * 127       (1 MB)
__device__ float    g_f1[BN];            // per-row logit factor: maxa*INV_T/(127*127)
__device__ float    g_pos[BN];           // positive logit (fp32-exact path)
__device__ float    g_partial[BN];       // per-row loss
__device__ int      g_is64;              // index dtype flag
__device__ int      g_count;             // last-block counter (reset each replay)

// ---------------------------------------------------------------------------
// Normalize z1/z2 in fp32; quantize both to int8 (z1 per-row scale, z2 flat
// 127); positive logit in full fp32. One warp per row. Block 0 / warp 0 also
// detects index dtype (values < 8192 => int64 has all-zero high words) and
// resets the completion counter for this graph replay.
// ---------------------------------------------------------------------------
__global__ void norm_kernel(const float* __restrict__ z1,
                            const float* __restrict__ z2,
                            const int* __restrict__ raw) {
    const int warp = threadIdx.x >> 5;
    const int lane = threadIdx.x & 31;

    if (blockIdx.x == 0 && warp == 0) {
        const int nz = (raw[2 * lane + 1] != 0) | (raw[2 * (lane + 32) + 1] != 0);
        const unsigned bal = __ballot_sync(0xffffffffu, nz);
        if (lane == 0) { g_is64 = (bal == 0u) ? 1 : 0; g_count = 0; }
    }

    const int row = blockIdx.x * 8 + warp;
    if (row >= BN) return;

    float4 a = reinterpret_cast<const float4*>(z1 + (size_t)row * DN)[lane];
    float4 b = reinterpret_cast<const float4*>(z2 + (size_t)row * DN)[lane];

    float sa = a.x * a.x + a.y * a.y + a.z * a.z + a.w * a.w;
    float sb = b.x * b.x + b.y * b.y + b.z * b.z + b.w * b.w;
    #pragma unroll
    for (int o = 16; o; o >>= 1) {
        sa += __shfl_xor_sync(0xffffffffu, sa, o);
        sb += __shfl_xor_sync(0xffffffffu, sb, o);
    }
    const float inva = 1.0f / fmaxf(sqrtf(sa), 1e-12f);
    const float invb = 1.0f / fmaxf(sqrtf(sb), 1e-12f);

    a.x *= inva; a.y *= inva; a.z *= inva; a.w *= inva;
    b.x *= invb; b.y *= invb; b.z *= invb; b.w *= invb;

    // per-row max |z1 elem| for tight quantization scale
    float m = fmaxf(fmaxf(fabsf(a.x), fabsf(a.y)), fmaxf(fabsf(a.z), fabsf(a.w)));
    #pragma unroll
    for (int o = 16; o; o >>= 1) m = fmaxf(m, __shfl_xor_sync(0xffffffffu, m, o));
    m = fmaxf(m, 1e-12f);
    const float s1 = 127.0f / m;

    const int qa0 = __float2int_rn(a.x * s1);
    const int qa1 = __float2int_rn(a.y * s1);
    const int qa2 = __float2int_rn(a.z * s1);
    const int qa3 = __float2int_rn(a.w * s1);
    g_z1q[(size_t)row * 32 + lane] =
        (qa0 & 0xff) | ((qa1 & 0xff) << 8) | ((qa2 & 0xff) << 16) | (qa3 << 24);

    const int qb0 = __float2int_rn(b.x * 127.0f);
    const int qb1 = __float2int_rn(b.y * 127.0f);
    const int qb2 = __float2int_rn(b.z * 127.0f);
    const int qb3 = __float2int_rn(b.w * 127.0f);
    g_z2q[(size_t)row * 32 + lane] =
        (qb0 & 0xff) | ((qb1 & 0xff) << 8) | ((qb2 & 0xff) << 16) | (qb3 << 24);

    if (lane == 0) g_f1[row] = m * (INV_T / (127.0f * 127.0f));

    // positive logit, full fp32
    float d = a.x * b.x + a.y * b.y + a.z * b.z + a.w * b.w;
    #pragma unroll
    for (int o = 16; o; o >>= 1) d += __shfl_xor_sync(0xffffffffu, d, o);
    if (lane == 0) g_pos[row] = d * INV_T;
}

// ---------------------------------------------------------------------------
// Gather v6: v4 structure (high occupancy, no launch_bounds cap) but the
// per-wave 3-shuffle reduce is HOISTED out of the loop. Loop body is just
// idx-shuffle + LDG.128 + 4 DP4A into independent vals[i] (no loop-carried
// chain -> natural load overlap). Epilogue: 3-stage recursive-halving
// transpose-reduce across the 8-lane group (7 shuffles, depth 3, vs 24/24).
// Lane (q,s) ends owning negative w*32 + 4*s + q -> one __expf per thread.
// The last block to finish performs the deterministic mean.
// ---------------------------------------------------------------------------
__global__ void __launch_bounds__(256)
gather_kernel(const int* __restrict__ raw, float* __restrict__ out) {
    __shared__ float s_red[8];
    __shared__ float s_sum[256];
    __shared__ bool  s_last;

    const int b    = blockIdx.x;
    const int t    = threadIdx.x;
    const int w    = t >> 5;
    const int lane = t & 31;
    const int s    = lane & 7;    // lane within 8-lane row group
    const int q    = lane >> 3;   // which of 4 rows per LDG wave

    // hoist the per-row scalars so their L2 latency overlaps the dot loop
    const float f1  = __ldg(&g_f1[b]);
    const float pos = __ldg(&g_pos[b]);

    // this lane's 16 z1 bytes (elements [s*16, s*16+16))
    const uint4 z1v =
        reinterpret_cast<const uint4*>(g_z1q)[(size_t)b * 8 + s];

    const int kbase = b * KN + w * 32 + lane;
    const int myidx = g_is64 ? raw[2 * kbase] : raw[kbase];

    // Loop: vals[i] = this lane's 16-byte partial dot of wave i's row.
    // No cross-iteration dependence, no in-loop shuffles on the data path.
    const uint4* z2p = reinterpret_cast<const uint4*>(g_z2q);
    int vals[8];
    #pragma unroll
    for (int i = 0; i < 8; i++) {
        const int row = __shfl_sync(0xffffffffu, myidx, 4 * i + q);
        const uint4 v = z2p[(size_t)row * 8 + s];
        int acc;
        acc = __dp4a((int)v.x, (int)z1v.x, 0);
        acc = __dp4a((int)v.y, (int)z1v.y, acc);
        acc = __dp4a((int)v.z, (int)z1v.z, acc);
        acc = __dp4a((int)v.w, (int)z1v.w, acc);
        vals[i] = acc;
    }

    // Transpose-reduce across the 8-lane group: after 3 stages lane s holds
    // sum over the group of vals[s]  (7 shuffles total, depth 3).
    // Stage 1 (offset 1): keep index parity == s&1.
    int y[4];
    {
        const int k = s & 1;
        #pragma unroll
        for (int j = 0; j < 4; j++) {
            const int mine = k ? vals[2 * j + 1] : vals[2 * j];
            const int send = k ? vals[2 * j]     : vals[2 * j + 1];
            y[j] = mine + __shfl_xor_sync(0xffffffffu, send, 1);
        }
    }
    // Stage 2 (offset 2): keep j parity == (s>>1)&1.
    int z[2];
    {
        const int k = (s >> 1) & 1;
        #pragma unroll
        for (int j = 0; j < 2; j++) {
            const int mine = k ? y[2 * j + 1] : y[2 * j];
            const int send = k ? y[2 * j]     : y[2 * j + 1];
            z[j] = mine + __shfl_xor_sync(0xffffffffu, send, 2);
        }
    }
    // Stage 3 (offset 4): keep z parity == (s>>2)&1.
    int mydot;
    {
        const int k = (s >> 2) & 1;
        const int mine = k ? z[1] : z[0];
        const int send = k ? z[0] : z[1];
        mydot = mine + __shfl_xor_sync(0xffffffffu, send, 4);
    }

    // |logit| <= ~14.3 -> no max-shift needed in fp32.
    float e = __expf((float)mydot * f1);
    #pragma unroll
    for (int o = 16; o; o >>= 1) e += __shfl_xor_sync(0xffffffffu, e, o);
    if (lane == 0) s_red[w] = e;
    __syncthreads();

    if (t == 0) {
        float tot = s_red[0] + s_red[1] + s_red[2] + s_red[3]
                  + s_red[4] + s_red[5] + s_red[6] + s_red[7];
        tot += __expf(pos);
        g_partial[b] = logf(tot) - pos;   // -log_softmax(logits)[0]
        __threadfence();
        const int c = atomicAdd(&g_count, 1);
        s_last = (c == BN - 1);
    }
    __syncthreads();

    // Last finishing block performs the mean (deterministic order).
    if (s_last) {
        const float4* p4 = reinterpret_cast<const float4*>(g_partial);
        float a = 0.0f;
        #pragma unroll
        for (int j = 0; j < 8; j++) {
            const float4 vv = __ldcg(p4 + t + j * 256);
            a += (vv.x + vv.y) + (vv.z + vv.w);
        }
        s_sum[t] = a;
        __syncthreads();
        #pragma unroll
        for (int o = 128; o; o >>= 1) {
            if (t < o) s_sum[t] += s_sum[t + o];
            __syncthreads();
        }
        if (t == 0) out[0] = s_sum[0] / (float)BN;
    }
}

extern "C" void kernel_launch(void* const* d_in, const int* in_sizes, int n_in,
                              void* d_out, int out_size) {
    const float* z1  = (const float*)d_in[0];
    const float* z2  = (const float*)d_in[1];
    const int*   neg = (const int*)d_in[2];   // raw view; width detected on-device
    float* out = (float*)d_out;

    norm_kernel<<<BN / 8, 256>>>(z1, z2, neg);
    gather_kernel<<<BN, 256>>>(neg, out);
}